// round 3
// baseline (speedup 1.0000x reference)
#include <cuda_runtime.h>
#include <math.h>

#define DIM        64
#define KCB        512
#define CHUNK_ROWS 32
#define NTH        256
#define GRID       148

// ---------------- device scratch (no allocation allowed) ----------------
__device__ float g_ET[KCB * DIM];   // transposed codebook [K][D]
__device__ float g_esq[KCB];        // ||e_k||^2
__device__ float g_loss;            // sum of (q-x)^2
__device__ int   g_cnt[KCB];        // histogram of indices

// ---------------- helpers ----------------
__device__ __forceinline__ unsigned sortkey(float f) {
    unsigned u = __float_as_uint(f);
    return (u & 0x80000000u) ? ~u : (u | 0x80000000u);
}
__device__ __forceinline__ unsigned long long pack2(float x) {
    unsigned long long r;
    asm("mov.b64 %0, {%1, %1};" : "=l"(r) : "f"(x));
    return r;
}
__device__ __forceinline__ void unpack2(unsigned long long v, float& lo, float& hi) {
    asm("mov.b64 {%0, %1}, %2;" : "=f"(lo), "=f"(hi) : "l"(v));
}

// ---------------- prep: esq, transposed codebook, zero accumulators ----------------
__global__ void vq_prep(const float* __restrict__ E) {
    int k = threadIdx.x;  // 512 threads
    float s = 0.f;
    #pragma unroll
    for (int d = 0; d < DIM; d++) {
        float v = E[d * KCB + k];      // coalesced across k
        s = fmaf(v, v, s);
        g_ET[k * DIM + d] = v;
    }
    g_esq[k] = s;
    g_cnt[k] = 0;
    if (k == 0) g_loss = 0.f;
}

// ---------------- main kernel ----------------
// smem: Esm[64*512] | xs[32*64] | esq[512] | hist[512 int] | lred[8]
static const int SMEM_FLOATS = DIM * KCB + CHUNK_ROWS * DIM + KCB + KCB + 8;
static const int SMEM_BYTES  = SMEM_FLOATS * 4;

__global__ void __launch_bounds__(NTH, 1)
vq_main(const float* __restrict__ x, const float* __restrict__ E,
        float* __restrict__ quant, float* __restrict__ enc,
        float* __restrict__ idxf, float* __restrict__ dist, int nRows)
{
    extern __shared__ float sm[];
    float* Esm  = sm;                               // 32768
    float* xs   = Esm + DIM * KCB;                  // 2048
    float* esq  = xs + CHUNK_ROWS * DIM;            // 512
    int*   hist = (int*)(esq + KCB);                // 512
    float* lred = (float*)(hist + KCB);             // 8

    const int tid  = threadIdx.x;
    const int lane = tid & 31;
    const int w    = tid >> 5;
    const int rbase = w << 2;                       // warp handles rows rbase..rbase+3

    // Load codebook to smem (float4, coalesced)
    for (int i = tid; i < (DIM * KCB) / 4; i += NTH)
        ((float4*)Esm)[i] = ((const float4*)E)[i];
    for (int i = tid; i < KCB; i += NTH) { esq[i] = g_esq[i]; hist[i] = 0; }
    __syncthreads();

    float lossAcc = 0.f;
    const int nChunks = nRows / CHUNK_ROWS;

    for (int chunk = blockIdx.x; chunk < nChunks; chunk += gridDim.x) {
        const int row0 = chunk * CHUNK_ROWS;
        __syncthreads();   // prior iteration done reading xs
        for (int i = tid; i < (CHUNK_ROWS * DIM) / 4; i += NTH)
            ((float4*)xs)[i] = ((const float4*)(x + (size_t)row0 * DIM))[i];
        __syncthreads();

        // per-warp: cache x halves and ||x||^2 for the 4 rows
        float xsq[4], x0v[4], x1v[4];
        #pragma unroll
        for (int r = 0; r < 4; r++) {
            float a = xs[(rbase + r) * DIM + lane];
            float b = xs[(rbase + r) * DIM + 32 + lane];
            x0v[r] = a; x1v[r] = b;
            float s = a * a + b * b;
            #pragma unroll
            for (int o = 16; o > 0; o >>= 1) s += __shfl_xor_sync(~0u, s, o);
            xsq[r] = s;
        }

        // register-blocked dot products: 4 rows x 8 k-pairs per thread, f32x2 FMAs
        unsigned long long acc[4][8];
        #pragma unroll
        for (int r = 0; r < 4; r++)
            #pragma unroll
            for (int i = 0; i < 8; i++) acc[r][i] = 0ull;

        #pragma unroll 4
        for (int d = 0; d < DIM; d++) {
            unsigned long long av[4];
            #pragma unroll
            for (int r = 0; r < 4; r++)
                av[r] = pack2(xs[(rbase + r) * DIM + d]);   // broadcast LDS
            const float* er = Esm + d * KCB + 2 * lane;
            unsigned long long bv[8];
            #pragma unroll
            for (int i = 0; i < 8; i++)
                bv[i] = *reinterpret_cast<const unsigned long long*>(er + 64 * i);
            #pragma unroll
            for (int r = 0; r < 4; r++)
                #pragma unroll
                for (int i = 0; i < 8; i++)
                    asm("fma.rn.f32x2 %0, %1, %2, %0;"
                        : "+l"(acc[r][i]) : "l"(av[r]), "l"(bv[i]));
        }

        // epilogue per row
        #pragma unroll
        for (int r = 0; r < 4; r++) {
            const int row = row0 + rbase + r;
            unsigned long long best = ~0ull;
            #pragma unroll
            for (int i = 0; i < 8; i++) {
                float dot0, dot1;
                unpack2(acc[r][i], dot0, dot1);
                const int k0 = 2 * (lane + 32 * i);
                float2 es = *(const float2*)(esq + k0);
                float d0 = fmaf(-2.f, dot0, xsq[r] + es.x);
                float d1 = fmaf(-2.f, dot1, xsq[r] + es.y);
                *(float2*)(dist + (size_t)row * KCB + k0) = make_float2(d0, d1);
                unsigned long long key0 =
                    ((unsigned long long)sortkey(d0) << 32) | (unsigned)k0;
                unsigned long long key1 =
                    ((unsigned long long)sortkey(d1) << 32) | (unsigned)(k0 + 1);
                if (key0 < best) best = key0;
                if (key1 < best) best = key1;
            }
            #pragma unroll
            for (int o = 16; o > 0; o >>= 1) {
                unsigned long long other = __shfl_xor_sync(~0u, best, o);
                if (other < best) best = other;
            }
            const int bk = (int)(best & 0xFFFFFFFFu);   // argmin, lowest-index tie-break

            // quantized gather (coalesced from transposed codebook in L2)
            float q0 = g_ET[bk * DIM + lane];
            float q1 = g_ET[bk * DIM + 32 + lane];
            // straight-through replay, bit-faithful to reference: x + (q - x)
            quant[(size_t)row * DIM + lane]      = x0v[r] + (q0 - x0v[r]);
            quant[(size_t)row * DIM + 32 + lane] = x1v[r] + (q1 - x1v[r]);
            float e0 = q0 - x0v[r], e1 = q1 - x1v[r];
            lossAcc += e0 * e0 + e1 * e1;

            // one-hot encodings row (full write, no separate memset pass)
            const size_t ebase = (size_t)row * KCB;
            #pragma unroll
            for (int i = 0; i < 8; i++) {
                const int k0 = 2 * (lane + 32 * i);
                *(float2*)(enc + ebase + k0) =
                    make_float2(k0 == bk ? 1.f : 0.f, (k0 + 1) == bk ? 1.f : 0.f);
            }
            if (lane == 0) {
                idxf[row] = (float)bk;
                atomicAdd(&hist[bk], 1);
            }
        }
    }

    // block reductions
    #pragma unroll
    for (int o = 16; o > 0; o >>= 1) lossAcc += __shfl_xor_sync(~0u, lossAcc, o);
    __syncthreads();
    if (lane == 0) lred[w] = lossAcc;
    __syncthreads();
    if (tid == 0) {
        float s = 0.f;
        #pragma unroll
        for (int i = 0; i < 8; i++) s += lred[i];
        atomicAdd(&g_loss, s);
    }
    for (int i = tid; i < KCB; i += NTH)
        if (hist[i]) atomicAdd(&g_cnt[i], hist[i]);
}

// ---------------- finalize: loss + perplexity ----------------
__global__ void vq_finalize(float* __restrict__ loss_out,
                            float* __restrict__ perp_out,
                            float invN, float invND)
{
    __shared__ float red[16];
    int t = threadIdx.x;  // 512
    float p = (float)g_cnt[t] * invN;
    float v = p * logf(p + 1e-10f);
    #pragma unroll
    for (int o = 16; o > 0; o >>= 1) v += __shfl_xor_sync(~0u, v, o);
    if ((t & 31) == 0) red[t >> 5] = v;
    __syncthreads();
    if (t == 0) {
        float s = 0.f;
        #pragma unroll
        for (int i = 0; i < 16; i++) s += red[i];
        *perp_out = expf(-s);
        *loss_out = 1.25f * g_loss * invND;   // q_latent + 0.25*e_latent (numerically equal)
    }
}

// ---------------- launch ----------------
extern "C" void kernel_launch(void* const* d_in, const int* in_sizes, int n_in,
                              void* d_out, int out_size)
{
    const float* x = (const float*)d_in[0];
    // d_in[1] = context (unused)
    const float* E = (const float*)d_in[2];
    const int N = in_sizes[0] / DIM;      // 65536

    float* out = (float*)d_out;
    // Output layout: quantized | loss | perplexity | encodings | indices | distances
    const size_t q_off    = 0;
    const size_t loss_off = (size_t)N * DIM;
    const size_t perp_off = loss_off + 1;
    const size_t enc_off  = perp_off + 1;
    const size_t idx_off  = enc_off + (size_t)N * KCB;
    const size_t dist_off = idx_off + (size_t)N;

    cudaFuncSetAttribute(vq_main, cudaFuncAttributeMaxDynamicSharedMemorySize,
                         SMEM_BYTES);

    vq_prep<<<1, KCB>>>(E);
    vq_main<<<GRID, NTH, SMEM_BYTES>>>(x, E,
                                       out + q_off, out + enc_off,
                                       out + idx_off, out + dist_off, N);
    vq_finalize<<<1, KCB>>>(out + loss_off, out + perp_off,
                            1.0f / (float)N, 1.0f / ((float)N * (float)DIM));
}

// round 4
// speedup vs baseline: 1.1752x; 1.1752x over previous
#include <cuda_runtime.h>
#include <math.h>

#define DIM        64
#define KCB        512
#define CHUNK_ROWS 64
#define NTH        256
#define GRID       148

typedef unsigned long long ull;

// ---------------- device scratch (no allocation allowed) ----------------
__device__ float g_ET[KCB * DIM];   // transposed codebook [K][D]
__device__ float g_loss;            // sum of (q-x)^2
__device__ int   g_cnt[KCB];        // histogram of indices

// ---------------- helpers ----------------
__device__ __forceinline__ unsigned sortkey(float f) {
    unsigned u = __float_as_uint(f);
    return (u & 0x80000000u) ? ~u : (u | 0x80000000u);
}
__device__ __forceinline__ ull pack2(float x) {
    ull r;
    asm("mov.b64 %0, {%1, %1};" : "=l"(r) : "f"(x));
    return r;
}
__device__ __forceinline__ ull pack_pair(float lo, float hi) {
    ull r;
    asm("mov.b64 %0, {%1, %2};" : "=l"(r) : "f"(lo), "f"(hi));
    return r;
}
__device__ __forceinline__ void unpack2(ull v, float& lo, float& hi) {
    asm("mov.b64 {%0, %1}, %2;" : "=f"(lo), "=f"(hi) : "l"(v));
}

// ---------------- prep: transpose codebook + zero accumulators --------
// 128 blocks x 256 threads: one element per thread, coalesced writes.
__global__ void vq_prep(const float* __restrict__ E) {
    int idx = blockIdx.x * blockDim.x + threadIdx.x;   // 0..32767
    int k = idx >> 6;          // idx / DIM
    int d = idx & 63;          // idx % DIM
    g_ET[idx] = E[d * KCB + k];
    if (idx < KCB) g_cnt[idx] = 0;
    if (idx == 0)  g_loss = 0.f;
}

// ---------------- main kernel ----------------
// smem: Esm[64*512] | xs[64*64] | esq[512] | hist[512 int] | lred[8]
static const int SMEM_FLOATS = DIM * KCB + CHUNK_ROWS * DIM + KCB + KCB + 8;
static const int SMEM_BYTES  = SMEM_FLOATS * 4;

__global__ void __launch_bounds__(NTH, 1)
vq_main(const float* __restrict__ x, const float* __restrict__ E,
        float* __restrict__ quant, float* __restrict__ enc,
        float* __restrict__ idxf, float* __restrict__ dist, int nRows)
{
    extern __shared__ float sm[];
    float* Esm  = sm;                               // 32768 floats
    float* xs   = Esm + DIM * KCB;                  // 4096 floats
    float* esq  = xs + CHUNK_ROWS * DIM;            // 512 floats
    int*   hist = (int*)(esq + KCB);                // 512 ints
    float* lred = (float*)(hist + KCB);             // 8 floats

    const int tid   = threadIdx.x;
    const int lane  = tid & 31;
    const int w     = tid >> 5;
    const int rbase = w << 3;                       // warp owns 8 rows

    // codebook -> smem (float4, coalesced)
    for (int i = tid; i < (DIM * KCB) / 4; i += NTH)
        ((float4*)Esm)[i] = ((const float4*)E)[i];
    __syncthreads();
    // esq from smem codebook (column reads: lane k%32 -> distinct banks, conflict-free)
    for (int k = tid; k < KCB; k += NTH) {
        float s = 0.f;
        #pragma unroll
        for (int d = 0; d < DIM; d++) {
            float v = Esm[d * KCB + k];
            s = fmaf(v, v, s);
        }
        esq[k]  = s;
        hist[k] = 0;
    }
    __syncthreads();

    float lossAcc = 0.f;
    const int nChunks = nRows / CHUNK_ROWS;

    for (int chunk = blockIdx.x; chunk < nChunks; chunk += gridDim.x) {
        const int row0 = chunk * CHUNK_ROWS;
        __syncthreads();   // previous epilogue done reading xs
        for (int i = tid; i < (CHUNK_ROWS * DIM) / 4; i += NTH)
            ((float4*)xs)[i] = ((const float4*)(x + (size_t)row0 * DIM))[i];
        __syncthreads();

        // ---- dot products: 8 rows x 4 k-groups x 2 pairs, packed f32x2 FMAs
        ull acc[8][4][2];
        #pragma unroll
        for (int r = 0; r < 8; r++)
            #pragma unroll
            for (int g = 0; g < 4; g++) { acc[r][g][0] = 0ull; acc[r][g][1] = 0ull; }

        #pragma unroll 2
        for (int d4 = 0; d4 < DIM / 4; d4++) {
            float4 av4[8];                           // broadcast LDS.128 per row
            #pragma unroll
            for (int r = 0; r < 8; r++)
                av4[r] = *(const float4*)(xs + (rbase + r) * DIM + d4 * 4);
            #pragma unroll
            for (int dd = 0; dd < 4; dd++) {
                const float* er = Esm + (d4 * 4 + dd) * KCB + 4 * lane;
                ull bv[4][2];
                #pragma unroll
                for (int g = 0; g < 4; g++) {        // LDS.128, conflict-free
                    float4 b4 = *(const float4*)(er + 128 * g);
                    bv[g][0] = pack_pair(b4.x, b4.y);
                    bv[g][1] = pack_pair(b4.z, b4.w);
                }
                #pragma unroll
                for (int r = 0; r < 8; r++) {
                    float a = (dd == 0) ? av4[r].x : (dd == 1) ? av4[r].y
                            : (dd == 2) ? av4[r].z : av4[r].w;
                    ull av = pack2(a);
                    #pragma unroll
                    for (int g = 0; g < 4; g++) {
                        asm("fma.rn.f32x2 %0, %1, %2, %0;"
                            : "+l"(acc[r][g][0]) : "l"(av), "l"(bv[g][0]));
                        asm("fma.rn.f32x2 %0, %1, %2, %0;"
                            : "+l"(acc[r][g][1]) : "l"(av), "l"(bv[g][1]));
                    }
                }
            }
        }

        // ---- epilogue per row
        #pragma unroll
        for (int r = 0; r < 8; r++) {
            const int row = row0 + rbase + r;
            const float a0 = xs[(rbase + r) * DIM + lane];
            const float a1 = xs[(rbase + r) * DIM + 32 + lane];
            float s = a0 * a0 + a1 * a1;
            #pragma unroll
            for (int o = 16; o > 0; o >>= 1) s += __shfl_xor_sync(~0u, s, o);
            const float xsq = s;

            ull best = ~0ull;
            #pragma unroll
            for (int g = 0; g < 4; g++) {
                const int k0 = 128 * g + 4 * lane;
                float4 es = *(const float4*)(esq + k0);
                float t0, t1, t2, t3;
                unpack2(acc[r][g][0], t0, t1);
                unpack2(acc[r][g][1], t2, t3);
                float d0 = fmaf(-2.f, t0, xsq + es.x);
                float d1 = fmaf(-2.f, t1, xsq + es.y);
                float d2 = fmaf(-2.f, t2, xsq + es.z);
                float d3 = fmaf(-2.f, t3, xsq + es.w);
                // dist base is only 8B-aligned (offset ≡ 2 mod 4 elems) -> STG.64
                float* dp = dist + (size_t)row * KCB + k0;
                *(float2*)(dp)     = make_float2(d0, d1);
                *(float2*)(dp + 2) = make_float2(d2, d3);
                ull key;
                key = ((ull)sortkey(d0) << 32) | (unsigned)(k0);
                if (key < best) best = key;
                key = ((ull)sortkey(d1) << 32) | (unsigned)(k0 + 1);
                if (key < best) best = key;
                key = ((ull)sortkey(d2) << 32) | (unsigned)(k0 + 2);
                if (key < best) best = key;
                key = ((ull)sortkey(d3) << 32) | (unsigned)(k0 + 3);
                if (key < best) best = key;
            }
            #pragma unroll
            for (int o = 16; o > 0; o >>= 1) {
                ull other = __shfl_xor_sync(~0u, best, o);
                if (other < best) best = other;
            }
            const int bk = (int)(best & 0xFFFFFFFFu);  // lowest-index tie-break

            // quantized gather (coalesced from transposed codebook, L2-resident)
            const float q0 = __ldg(g_ET + bk * DIM + lane);
            const float q1 = __ldg(g_ET + bk * DIM + 32 + lane);
            quant[(size_t)row * DIM + lane]      = a0 + (q0 - a0);
            quant[(size_t)row * DIM + 32 + lane] = a1 + (q1 - a1);
            const float e0 = q0 - a0, e1 = q1 - a1;
            lossAcc += e0 * e0 + e1 * e1;

            // one-hot encodings row (8B-aligned base -> STG.64)
            float* ep = enc + (size_t)row * KCB;
            #pragma unroll
            for (int g = 0; g < 4; g++) {
                const int k0 = 128 * g + 4 * lane;
                *(float2*)(ep + k0) =
                    make_float2(k0 == bk ? 1.f : 0.f, (k0 + 1) == bk ? 1.f : 0.f);
                *(float2*)(ep + k0 + 2) =
                    make_float2((k0 + 2) == bk ? 1.f : 0.f, (k0 + 3) == bk ? 1.f : 0.f);
            }
            if (lane == 0) {
                idxf[row] = (float)bk;
                atomicAdd(&hist[bk], 1);
            }
        }
    }

    // block reductions
    #pragma unroll
    for (int o = 16; o > 0; o >>= 1) lossAcc += __shfl_xor_sync(~0u, lossAcc, o);
    __syncthreads();
    if (lane == 0) lred[w] = lossAcc;
    __syncthreads();
    if (tid == 0) {
        float s = 0.f;
        #pragma unroll
        for (int i = 0; i < 8; i++) s += lred[i];
        atomicAdd(&g_loss, s);
    }
    for (int i = tid; i < KCB; i += NTH)
        if (hist[i]) atomicAdd(&g_cnt[i], hist[i]);
}

// ---------------- finalize: loss + perplexity ----------------
__global__ void vq_finalize(float* __restrict__ loss_out,
                            float* __restrict__ perp_out,
                            float invN, float invND)
{
    __shared__ float red[16];
    int t = threadIdx.x;  // 512
    float p = (float)g_cnt[t] * invN;
    float v = p * logf(p + 1e-10f);
    #pragma unroll
    for (int o = 16; o > 0; o >>= 1) v += __shfl_xor_sync(~0u, v, o);
    if ((t & 31) == 0) red[t >> 5] = v;
    __syncthreads();
    if (t == 0) {
        float s = 0.f;
        #pragma unroll
        for (int i = 0; i < 16; i++) s += red[i];
        *perp_out = expf(-s);
        *loss_out = 1.25f * g_loss * invND;   // q_latent + 0.25*e_latent
    }
}

// ---------------- launch ----------------
extern "C" void kernel_launch(void* const* d_in, const int* in_sizes, int n_in,
                              void* d_out, int out_size)
{
    const float* x = (const float*)d_in[0];
    // d_in[1] = context (unused)
    const float* E = (const float*)d_in[2];
    const int N = in_sizes[0] / DIM;      // 65536

    float* out = (float*)d_out;
    // Output layout: quantized | loss | perplexity | encodings | indices | distances
    const size_t q_off    = 0;
    const size_t loss_off = (size_t)N * DIM;
    const size_t perp_off = loss_off + 1;
    const size_t enc_off  = perp_off + 1;
    const size_t idx_off  = enc_off + (size_t)N * KCB;
    const size_t dist_off = idx_off + (size_t)N;

    cudaFuncSetAttribute(vq_main, cudaFuncAttributeMaxDynamicSharedMemorySize,
                         SMEM_BYTES);

    vq_prep<<<(KCB * DIM) / NTH, NTH>>>(E);
    vq_main<<<GRID, NTH, SMEM_BYTES>>>(x, E,
                                       out + q_off, out + enc_off,
                                       out + idx_off, out + dist_off, N);
    vq_finalize<<<1, KCB>>>(out + loss_off, out + perp_off,
                            1.0f / (float)N, 1.0f / ((float)N * (float)DIM));
}

// round 5
// speedup vs baseline: 1.3803x; 1.1745x over previous
#include <cuda_runtime.h>
#include <math.h>

#define DIM        64
#define KCB        512
#define CHUNK_ROWS 64
#define NTH        256
#define GRID       148

typedef unsigned long long ull;

// ---------------- device scratch (no allocation allowed) ----------------
__device__ float g_ET[KCB * DIM];   // transposed codebook [K][D]
__device__ float g_loss;            // sum of (q-x)^2
__device__ int   g_cnt[KCB];        // histogram of indices

// ---------------- helpers ----------------
__device__ __forceinline__ ull pack2(float x) {
    ull r;
    asm("mov.b64 %0, {%1, %1};" : "=l"(r) : "f"(x));
    return r;
}
__device__ __forceinline__ void unpack2(ull v, float& lo, float& hi) {
    asm("mov.b64 {%0, %1}, %2;" : "=f"(lo), "=f"(hi) : "l"(v));
}

// ---------------- prep: tiled transpose (coalesced both sides) ----------
// grid (16,2), block (32,32). E is [64][512] -> g_ET [512][64].
__global__ void vq_prep(const float* __restrict__ E) {
    __shared__ float t[32][33];
    const int kb = blockIdx.x * 32, db = blockIdx.y * 32;
    t[threadIdx.y][threadIdx.x] = E[(db + threadIdx.y) * KCB + kb + threadIdx.x];
    __syncthreads();
    g_ET[(kb + threadIdx.y) * DIM + db + threadIdx.x] = t[threadIdx.x][threadIdx.y];
    if (blockIdx.x == 0 && blockIdx.y == 0) {
        int id = threadIdx.y * 32 + threadIdx.x;
        if (id < KCB) g_cnt[id] = 0;
        if (id == 0)  g_loss = 0.f;
    }
}

// ---------------- main kernel ----------------
// smem: Esm[64*512] | xs[64*64] | esq[512] | hist[512 int] | lred[8]
static const int SMEM_FLOATS = DIM * KCB + CHUNK_ROWS * DIM + KCB + KCB + 8;
static const int SMEM_BYTES  = SMEM_FLOATS * 4;

__global__ void __launch_bounds__(NTH, 1)
vq_main(const float* __restrict__ x, const float* __restrict__ E,
        float* __restrict__ quant, float* __restrict__ enc,
        float* __restrict__ idxf, float* __restrict__ dist, int nRows)
{
    extern __shared__ float sm[];
    float* Esm  = sm;                               // 32768 floats
    float* xs   = Esm + DIM * KCB;                  // 4096 floats
    float* esq  = xs + CHUNK_ROWS * DIM;            // 512 floats
    int*   hist = (int*)(esq + KCB);                // 512 ints
    float* lred = (float*)(hist + KCB);             // 8 floats

    const int tid   = threadIdx.x;
    const int lane  = tid & 31;
    const int w     = tid >> 5;
    const int rbase = w << 3;                       // warp owns 8 rows

    // codebook -> smem (float4, coalesced)
    for (int i = tid; i < (DIM * KCB) / 4; i += NTH)
        ((float4*)Esm)[i] = ((const float4*)E)[i];
    __syncthreads();
    // esq from smem codebook (column reads, conflict-free)
    for (int k = tid; k < KCB; k += NTH) {
        float s = 0.f;
        #pragma unroll
        for (int d = 0; d < DIM; d++) {
            float v = Esm[d * KCB + k];
            s = fmaf(v, v, s);
        }
        esq[k]  = s;
        hist[k] = 0;
    }

    float lossAcc = 0.f;
    const int nChunks = nRows / CHUNK_ROWS;

    // prefetch first chunk into registers
    float4 pf[4];
    int chunk = blockIdx.x;
    if (chunk < nChunks) {
        const float4* src = (const float4*)(x + (size_t)chunk * CHUNK_ROWS * DIM);
        #pragma unroll
        for (int i = 0; i < 4; i++) pf[i] = src[tid + NTH * i];
    }

    for (; chunk < nChunks; chunk += GRID) {
        const int row0 = chunk * CHUNK_ROWS;
        // deposit prefetched x (previous epilogue's xs reads fenced by loop-end sync)
        #pragma unroll
        for (int i = 0; i < 4; i++) ((float4*)xs)[tid + NTH * i] = pf[i];
        __syncthreads();

        // issue next chunk's loads early; latency hidden behind d-loop
        const int next = chunk + GRID;
        if (next < nChunks) {
            const float4* src = (const float4*)(x + (size_t)next * CHUNK_ROWS * DIM);
            #pragma unroll
            for (int i = 0; i < 4; i++) pf[i] = src[tid + NTH * i];
        }

        // ---- dot products: 8 rows x 8 k-pair groups, packed f32x2 FMAs
        // lane owns k pairs {2*lane + 64*g}
        ull acc[8][8];
        #pragma unroll
        for (int r = 0; r < 8; r++)
            #pragma unroll
            for (int g = 0; g < 8; g++) acc[r][g] = 0ull;

        #pragma unroll 2
        for (int d2 = 0; d2 < DIM / 2; d2++) {
            float2 av2[8];                           // broadcast LDS.64 per row
            #pragma unroll
            for (int r = 0; r < 8; r++)
                av2[r] = *(const float2*)(xs + (rbase + r) * DIM + d2 * 2);
            #pragma unroll
            for (int dd = 0; dd < 2; dd++) {
                const float* er = Esm + (d2 * 2 + dd) * KCB + 2 * lane;
                ull bv[8];
                #pragma unroll
                for (int g = 0; g < 8; g++)          // LDS.64, 256B contiguous/warp
                    bv[g] = *reinterpret_cast<const ull*>(er + 64 * g);
                #pragma unroll
                for (int r = 0; r < 8; r++) {
                    ull av = pack2(dd == 0 ? av2[r].x : av2[r].y);
                    #pragma unroll
                    for (int g = 0; g < 8; g++)
                        asm("fma.rn.f32x2 %0, %1, %2, %0;"
                            : "+l"(acc[r][g]) : "l"(av), "l"(bv[g]));
                }
            }
        }

        // ---- epilogue per row
        #pragma unroll
        for (int r = 0; r < 8; r++) {
            const int row = row0 + rbase + r;
            const float a0 = xs[(rbase + r) * DIM + lane];
            const float a1 = xs[(rbase + r) * DIM + 32 + lane];
            float s = a0 * a0 + a1 * a1;
            #pragma unroll
            for (int o = 16; o > 0; o >>= 1) s += __shfl_xor_sync(~0u, s, o);
            const float xsq = s;

            // distances + per-lane argmin (ascending k => strict < keeps lowest)
            float bestv = __int_as_float(0x7F800000);  // +inf
            int   besti = 0;
            float* dp = dist + (size_t)row * KCB + 2 * lane;
            #pragma unroll
            for (int g = 0; g < 8; g++) {
                const int k0 = 2 * lane + 64 * g;
                float2 es = *(const float2*)(esq + k0);
                float t0, t1;
                unpack2(acc[r][g], t0, t1);
                float d0 = fmaf(-2.f, t0, xsq + es.x);
                float d1 = fmaf(-2.f, t1, xsq + es.y);
                __stcs((float2*)(dp + 64 * g), make_float2(d0, d1));  // 256B/warp
                if (d0 < bestv) { bestv = d0; besti = k0; }
                if (d1 < bestv) { bestv = d1; besti = k0 + 1; }
            }
            // cross-lane argmin, tie -> lowest index
            #pragma unroll
            for (int o = 16; o > 0; o >>= 1) {
                float ov = __shfl_xor_sync(~0u, bestv, o);
                int   oi = __shfl_xor_sync(~0u, besti, o);
                if (ov < bestv || (ov == bestv && oi < besti)) { bestv = ov; besti = oi; }
            }
            const int bk = besti;

            // quantized gather (coalesced from transposed codebook, L2-resident)
            const float q0 = __ldg(g_ET + bk * DIM + lane);
            const float q1 = __ldg(g_ET + bk * DIM + 32 + lane);
            __stcs(quant + (size_t)row * DIM + lane,      a0 + (q0 - a0));
            __stcs(quant + (size_t)row * DIM + 32 + lane, a1 + (q1 - a1));
            const float e0 = q0 - a0, e1 = q1 - a1;
            lossAcc += e0 * e0 + e1 * e1;

            // one-hot encodings row (256B contiguous per STG.64)
            float* ep = enc + (size_t)row * KCB + 2 * lane;
            #pragma unroll
            for (int g = 0; g < 8; g++) {
                const int k0 = 2 * lane + 64 * g;
                __stcs((float2*)(ep + 64 * g),
                       make_float2(k0 == bk ? 1.f : 0.f, (k0 + 1) == bk ? 1.f : 0.f));
            }
            if (lane == 0) {
                idxf[row] = (float)bk;
                atomicAdd(&hist[bk], 1);
            }
        }
        __syncthreads();   // epilogue done reading xs before next deposit
    }

    // block reductions
    #pragma unroll
    for (int o = 16; o > 0; o >>= 1) lossAcc += __shfl_xor_sync(~0u, lossAcc, o);
    if (lane == 0) lred[w] = lossAcc;
    __syncthreads();
    if (tid == 0) {
        float s = 0.f;
        #pragma unroll
        for (int i = 0; i < 8; i++) s += lred[i];
        atomicAdd(&g_loss, s);
    }
    for (int i = tid; i < KCB; i += NTH)
        if (hist[i]) atomicAdd(&g_cnt[i], hist[i]);
}

// ---------------- finalize: loss + perplexity ----------------
__global__ void vq_finalize(float* __restrict__ loss_out,
                            float* __restrict__ perp_out,
                            float invN, float invND)
{
    __shared__ float red[16];
    int t = threadIdx.x;  // 512
    float p = (float)g_cnt[t] * invN;
    float v = p * logf(p + 1e-10f);
    #pragma unroll
    for (int o = 16; o > 0; o >>= 1) v += __shfl_xor_sync(~0u, v, o);
    if ((t & 31) == 0) red[t >> 5] = v;
    __syncthreads();
    if (t == 0) {
        float s = 0.f;
        #pragma unroll
        for (int i = 0; i < 16; i++) s += red[i];
        *perp_out = expf(-s);
        *loss_out = 1.25f * g_loss * invND;   // q_latent + 0.25*e_latent
    }
}

// ---------------- launch ----------------
extern "C" void kernel_launch(void* const* d_in, const int* in_sizes, int n_in,
                              void* d_out, int out_size)
{
    const float* x = (const float*)d_in[0];
    // d_in[1] = context (unused)
    const float* E = (const float*)d_in[2];
    const int N = in_sizes[0] / DIM;      // 65536

    float* out = (float*)d_out;
    // Output layout: quantized | loss | perplexity | encodings | indices | distances
    const size_t q_off    = 0;
    const size_t loss_off = (size_t)N * DIM;
    const size_t perp_off = loss_off + 1;
    const size_t enc_off  = perp_off + 1;
    const size_t idx_off  = enc_off + (size_t)N * KCB;
    const size_t dist_off = idx_off + (size_t)N;

    cudaFuncSetAttribute(vq_main, cudaFuncAttributeMaxDynamicSharedMemorySize,
                         SMEM_BYTES);

    dim3 pgrid(KCB / 32, DIM / 32);
    vq_prep<<<pgrid, dim3(32, 32)>>>(E);
    vq_main<<<GRID, NTH, SMEM_BYTES>>>(x, E,
                                       out + q_off, out + enc_off,
                                       out + idx_off, out + dist_off, N);
    vq_finalize<<<1, KCB>>>(out + loss_off, out + perp_off,
                            1.0f / (float)N, 1.0f / ((float)N * (float)DIM));
}

// round 6
// speedup vs baseline: 1.4018x; 1.0156x over previous
#include <cuda_runtime.h>
#include <math.h>

#define DIM        64
#define KCB        512
#define CHUNK_ROWS 64
#define NTH        256
#define GRID       148

typedef unsigned long long ull;

// ---------------- device scratch (no allocation allowed) ----------------
__device__ float g_ET[KCB * DIM];   // transposed codebook [K][D]
__device__ float g_loss;            // sum of (q-x)^2
__device__ int   g_cnt[KCB];        // histogram of indices

// ---------------- helpers ----------------
__device__ __forceinline__ ull pack2(float x) {
    ull r;
    asm("mov.b64 %0, {%1, %1};" : "=l"(r) : "f"(x));
    return r;
}
__device__ __forceinline__ void unpack2(ull v, float& lo, float& hi) {
    asm("mov.b64 {%0, %1}, %2;" : "=f"(lo), "=f"(hi) : "l"(v));
}
__device__ __forceinline__ void cp16(unsigned dst, const void* src) {
    asm volatile("cp.async.cg.shared.global [%0], [%1], 16;" :: "r"(dst), "l"(src));
}
__device__ __forceinline__ void cp_commit() {
    asm volatile("cp.async.commit_group;");
}
__device__ __forceinline__ void cp_wait0() {
    asm volatile("cp.async.wait_group 0;");
}

// ---------------- prep: tiled transpose (coalesced both sides) ----------
__global__ void vq_prep(const float* __restrict__ E) {
    __shared__ float t[32][33];
    const int kb = blockIdx.x * 32, db = blockIdx.y * 32;
    t[threadIdx.y][threadIdx.x] = E[(db + threadIdx.y) * KCB + kb + threadIdx.x];
    __syncthreads();
    g_ET[(kb + threadIdx.y) * DIM + db + threadIdx.x] = t[threadIdx.x][threadIdx.y];
    if (blockIdx.x == 0 && blockIdx.y == 0) {
        int id = threadIdx.y * 32 + threadIdx.x;
        if (id < KCB) g_cnt[id] = 0;
        if (id == 0)  g_loss = 0.f;
    }
}

// ---------------- main kernel ----------------
// smem: Esm[64*512] | xs0[64*64] | xs1[64*64] | esq[512] | hist[512] | lred[8]
static const int XS0_OFF   = DIM * KCB;
static const int XS1_OFF   = XS0_OFF + CHUNK_ROWS * DIM;
static const int ESQ_OFF   = XS1_OFF + CHUNK_ROWS * DIM;
static const int HIST_OFF  = ESQ_OFF + KCB;
static const int LRED_OFF  = HIST_OFF + KCB;
static const int SMEM_BYTES = (LRED_OFF + 8) * 4;

__global__ void __launch_bounds__(NTH, 1)
vq_main(const float* __restrict__ x, const float* __restrict__ E,
        float* __restrict__ quant, float* __restrict__ enc,
        float* __restrict__ idxf, float* __restrict__ dist, int nRows)
{
    extern __shared__ float sm[];
    float* Esm  = sm;
    float* esq  = sm + ESQ_OFF;
    int*   hist = (int*)(sm + HIST_OFF);
    float* lred = sm + LRED_OFF;

    const int tid   = threadIdx.x;
    const int lane  = tid & 31;
    const int w     = tid >> 5;
    const int rbase = w << 3;                       // warp owns 8 rows

    unsigned smem_u32;
    {
        void* p = sm;
        asm("{ .reg .u64 t; cvta.to.shared.u64 t, %1; cvt.u32.u64 %0, t; }"
            : "=r"(smem_u32) : "l"(p));
    }
    const unsigned xs_u32[2] = { smem_u32 + XS0_OFF * 4, smem_u32 + XS1_OFF * 4 };

    // codebook -> smem (float4, coalesced)
    for (int i = tid; i < (DIM * KCB) / 4; i += NTH)
        ((float4*)Esm)[i] = ((const float4*)E)[i];
    __syncthreads();
    // esq (column reads, conflict-free per stride-1-in-k threads)
    for (int k = tid; k < KCB; k += NTH) {
        float s = 0.f;
        #pragma unroll
        for (int d = 0; d < DIM; d++) {
            float v = Esm[d * KCB + k];
            s = fmaf(v, v, s);
        }
        esq[k]  = s;
        hist[k] = 0;
    }
    __syncthreads();

    // per-lane esq registers: k pairs {2*lane + 64*g}
    float e0r[8], e1r[8];
    #pragma unroll
    for (int g = 0; g < 8; g++) {
        float2 e = *(const float2*)(esq + 2 * lane + 64 * g);
        e0r[g] = e.x; e1r[g] = e.y;
    }

    float lossAcc = 0.f;
    const int nChunks = nRows / CHUNK_ROWS;

    int chunk = blockIdx.x;
    if (chunk < nChunks) {
        const char* src = (const char*)(x + (size_t)chunk * CHUNK_ROWS * DIM) + tid * 16;
        #pragma unroll
        for (int i = 0; i < 4; i++)
            cp16(xs_u32[0] + tid * 16 + i * NTH * 16, src + i * NTH * 16);
        cp_commit();
    }

    int buf = 0;
    for (; chunk < nChunks; chunk += GRID) {
        const int row0 = chunk * CHUNK_ROWS;
        cp_wait0();
        __syncthreads();            // tile ready; previous epilogue done with other buf

        const int next = chunk + GRID;
        if (next < nChunks) {
            const char* src = (const char*)(x + (size_t)next * CHUNK_ROWS * DIM) + tid * 16;
            const unsigned d32 = xs_u32[buf ^ 1] + tid * 16;
            #pragma unroll
            for (int i = 0; i < 4; i++)
                cp16(d32 + i * NTH * 16, src + i * NTH * 16);
            cp_commit();
        }
        const float* xs = sm + (buf ? XS1_OFF : XS0_OFF);

        // ---- dot products: 8 rows x 8 k-pair groups, packed f32x2 FMAs
        ull acc[8][8];
        #pragma unroll
        for (int r = 0; r < 8; r++)
            #pragma unroll
            for (int g = 0; g < 8; g++) acc[r][g] = 0ull;

        #pragma unroll 2
        for (int d2 = 0; d2 < DIM / 2; d2++) {
            float2 av2[8];                           // broadcast LDS.64 per row
            #pragma unroll
            for (int r = 0; r < 8; r++)
                av2[r] = *(const float2*)(xs + (rbase + r) * DIM + d2 * 2);
            #pragma unroll
            for (int dd = 0; dd < 2; dd++) {
                const float* er = Esm + (d2 * 2 + dd) * KCB + 2 * lane;
                ull bv[8];
                #pragma unroll
                for (int g = 0; g < 8; g++)
                    bv[g] = *reinterpret_cast<const ull*>(er + 64 * g);
                #pragma unroll
                for (int r = 0; r < 8; r++) {
                    ull av = pack2(dd == 0 ? av2[r].x : av2[r].y);
                    #pragma unroll
                    for (int g = 0; g < 8; g++)
                        asm("fma.rn.f32x2 %0, %1, %2, %0;"
                            : "+l"(acc[r][g]) : "l"(av), "l"(bv[g]));
                }
            }
        }

        // ---- epilogue per row
        #pragma unroll
        for (int r = 0; r < 8; r++) {
            const int row = row0 + rbase + r;
            const float a0 = xs[(rbase + r) * DIM + lane];
            const float a1 = xs[(rbase + r) * DIM + 32 + lane];
            float s = a0 * a0 + a1 * a1;
            #pragma unroll
            for (int o = 16; o > 0; o >>= 1) s += __shfl_xor_sync(~0u, s, o);
            const float xsq = s;

            float bestv = __int_as_float(0x7F800000);  // +inf
            int   besti = 0;
            float* dp = dist + (size_t)row * KCB + 2 * lane;
            #pragma unroll
            for (int g = 0; g < 8; g++) {
                const int k0 = 2 * lane + 64 * g;
                float t0, t1;
                unpack2(acc[r][g], t0, t1);
                float d0 = fmaf(-2.f, t0, xsq + e0r[g]);
                float d1 = fmaf(-2.f, t1, xsq + e1r[g]);
                __stcs((float2*)(dp + 64 * g), make_float2(d0, d1));
                if (d0 < bestv) { bestv = d0; besti = k0; }
                if (d1 < bestv) { bestv = d1; besti = k0 + 1; }
            }
            #pragma unroll
            for (int o = 16; o > 0; o >>= 1) {
                float ov = __shfl_xor_sync(~0u, bestv, o);
                int   oi = __shfl_xor_sync(~0u, besti, o);
                if (ov < bestv || (ov == bestv && oi < besti)) { bestv = ov; besti = oi; }
            }
            const int bk = besti;

            const float q0 = __ldg(g_ET + bk * DIM + lane);
            const float q1 = __ldg(g_ET + bk * DIM + 32 + lane);
            __stcs(quant + (size_t)row * DIM + lane,      a0 + (q0 - a0));
            __stcs(quant + (size_t)row * DIM + 32 + lane, a1 + (q1 - a1));
            const float e0 = q0 - a0, e1 = q1 - a1;
            lossAcc += e0 * e0 + e1 * e1;

            float* ep = enc + (size_t)row * KCB + 2 * lane;
            #pragma unroll
            for (int g = 0; g < 8; g++) {
                const int k0 = 2 * lane + 64 * g;
                __stcs((float2*)(ep + 64 * g),
                       make_float2(k0 == bk ? 1.f : 0.f, (k0 + 1) == bk ? 1.f : 0.f));
            }
            if (lane == 0) {
                idxf[row] = (float)bk;
                atomicAdd(&hist[bk], 1);
            }
        }
        buf ^= 1;
    }

    // block reductions
    #pragma unroll
    for (int o = 16; o > 0; o >>= 1) lossAcc += __shfl_xor_sync(~0u, lossAcc, o);
    __syncthreads();
    if (lane == 0) lred[w] = lossAcc;
    __syncthreads();
    if (tid == 0) {
        float s = 0.f;
        #pragma unroll
        for (int i = 0; i < 8; i++) s += lred[i];
        atomicAdd(&g_loss, s);
    }
    for (int i = tid; i < KCB; i += NTH)
        if (hist[i]) atomicAdd(&g_cnt[i], hist[i]);
}

// ---------------- finalize: loss + perplexity ----------------
__global__ void vq_finalize(float* __restrict__ loss_out,
                            float* __restrict__ perp_out,
                            float invN, float invND)
{
    __shared__ float red[16];
    int t = threadIdx.x;  // 512
    float p = (float)g_cnt[t] * invN;
    float v = p * logf(p + 1e-10f);
    #pragma unroll
    for (int o = 16; o > 0; o >>= 1) v += __shfl_xor_sync(~0u, v, o);
    if ((t & 31) == 0) red[t >> 5] = v;
    __syncthreads();
    if (t == 0) {
        float s = 0.f;
        #pragma unroll
        for (int i = 0; i < 16; i++) s += red[i];
        *perp_out = expf(-s);
        *loss_out = 1.25f * g_loss * invND;   // q_latent + 0.25*e_latent
    }
}

// ---------------- launch ----------------
extern "C" void kernel_launch(void* const* d_in, const int* in_sizes, int n_in,
                              void* d_out, int out_size)
{
    const float* x = (const float*)d_in[0];
    // d_in[1] = context (unused)
    const float* E = (const float*)d_in[2];
    const int N = in_sizes[0] / DIM;      // 65536

    float* out = (float*)d_out;
    const size_t q_off    = 0;
    const size_t loss_off = (size_t)N * DIM;
    const size_t perp_off = loss_off + 1;
    const size_t enc_off  = perp_off + 1;
    const size_t idx_off  = enc_off + (size_t)N * KCB;
    const size_t dist_off = idx_off + (size_t)N;

    cudaFuncSetAttribute(vq_main, cudaFuncAttributeMaxDynamicSharedMemorySize,
                         SMEM_BYTES);

    dim3 pgrid(KCB / 32, DIM / 32);
    vq_prep<<<pgrid, dim3(32, 32)>>>(E);
    vq_main<<<GRID, NTH, SMEM_BYTES>>>(x, E,
                                       out + q_off, out + enc_off,
                                       out + idx_off, out + dist_off, N);
    vq_finalize<<<1, KCB>>>(out + loss_off, out + perp_off,
                            1.0f / (float)N, 1.0f / ((float)N * (float)DIM));
}

// round 7
// speedup vs baseline: 1.4742x; 1.0516x over previous
#include <cuda_runtime.h>
#include <math.h>

#define DIM        64
#define KCB        512
#define CHUNK_ROWS 64
#define NTH        256
#define GRID       148

typedef unsigned long long ull;

// ---------------- device scratch (no allocation allowed) ----------------
__device__ float g_ET[KCB * DIM];   // transposed codebook [K][D]
__device__ float g_loss;            // sum of (q-x)^2
__device__ int   g_cnt[KCB];        // histogram of indices

// ---------------- helpers ----------------
__device__ __forceinline__ ull pack2(float x) {
    ull r;
    asm("mov.b64 %0, {%1, %1};" : "=l"(r) : "f"(x));
    return r;
}
__device__ __forceinline__ void unpack2(ull v, float& lo, float& hi) {
    asm("mov.b64 {%0, %1}, %2;" : "=f"(lo), "=f"(hi) : "l"(v));
}
__device__ __forceinline__ void cp16(unsigned dst, const void* src) {
    asm volatile("cp.async.cg.shared.global [%0], [%1], 16;" :: "r"(dst), "l"(src));
}
__device__ __forceinline__ void cp_commit() {
    asm volatile("cp.async.commit_group;");
}
__device__ __forceinline__ void cp_wait0() {
    asm volatile("cp.async.wait_group 0;");
}
__device__ __forceinline__ void cp_wait1() {
    asm volatile("cp.async.wait_group 1;");
}

// ---------------- prep: tiled transpose (coalesced both sides) ----------
__global__ void vq_prep(const float* __restrict__ E) {
    __shared__ float t[32][33];
    const int kb = blockIdx.x * 32, db = blockIdx.y * 32;
    t[threadIdx.y][threadIdx.x] = E[(db + threadIdx.y) * KCB + kb + threadIdx.x];
    __syncthreads();
    g_ET[(kb + threadIdx.y) * DIM + db + threadIdx.x] = t[threadIdx.x][threadIdx.y];
    if (blockIdx.x == 0 && blockIdx.y == 0) {
        int id = threadIdx.y * 32 + threadIdx.x;
        if (id < KCB) g_cnt[id] = 0;
        if (id == 0)  g_loss = 0.f;
    }
}

// ---------------- main kernel ----------------
// smem: Esm[64*512] | per-warp xs (8 warps x 2 bufs x 512 floats) | esq | hist | lred
static const int XS_OFF    = DIM * KCB;                 // 32768
static const int XS_FLOATS = 8 * 2 * (8 * DIM);         // 8192
static const int ESQ_OFF   = XS_OFF + XS_FLOATS;        // 40960
static const int HIST_OFF  = ESQ_OFF + KCB;             // 41472
static const int LRED_OFF  = HIST_OFF + KCB;            // 41984
static const int SMEM_BYTES = (LRED_OFF + 8) * 4;

__global__ void __launch_bounds__(NTH, 1)
vq_main(const float* __restrict__ x, const float* __restrict__ E,
        float* __restrict__ quant, float* __restrict__ enc,
        float* __restrict__ idxf, float* __restrict__ dist, int nRows)
{
    extern __shared__ float sm[];
    float* Esm  = sm;
    float* esq  = sm + ESQ_OFF;
    int*   hist = (int*)(sm + HIST_OFF);
    float* lred = sm + LRED_OFF;

    const int tid   = threadIdx.x;
    const int lane  = tid & 31;
    const int w     = tid >> 5;

    unsigned smem_u32;
    {
        void* p = sm;
        asm("{ .reg .u64 t; cvta.to.shared.u64 t, %1; cvt.u32.u64 %0, t; }"
            : "=r"(smem_u32) : "l"(p));
    }
    // per-warp private x tile: 2 buffers x 512 floats (8 rows x 64)
    float* xw = sm + XS_OFF + w * 1024;
    const unsigned xw_u32 = smem_u32 + (XS_OFF + w * 1024) * 4;

    // codebook -> smem (float4, coalesced)
    for (int i = tid; i < (DIM * KCB) / 4; i += NTH)
        ((float4*)Esm)[i] = ((const float4*)E)[i];
    __syncthreads();
    // esq (column reads, conflict-free)
    for (int k = tid; k < KCB; k += NTH) {
        float s = 0.f;
        #pragma unroll
        for (int d = 0; d < DIM; d++) {
            float v = Esm[d * KCB + k];
            s = fmaf(v, v, s);
        }
        esq[k]  = s;
        hist[k] = 0;
    }
    __syncthreads();   // last block-wide barrier until the final reduction

    // per-lane esq registers: k pairs {2*lane + 64*g}
    float e0r[8], e1r[8];
    #pragma unroll
    for (int g = 0; g < 8; g++) {
        float2 e = *(const float2*)(esq + 2 * lane + 64 * g);
        e0r[g] = e.x; e1r[g] = e.y;
    }

    float lossAcc = 0.f;
    const int nChunks = nRows / CHUNK_ROWS;

    // warp-autonomous main loop: no block barriers, warps drift freely
    int chunk = blockIdx.x;
    if (chunk < nChunks) {
        // prologue: load this warp's 8 rows of chunk into buf0 (2048 B)
        const char* src = (const char*)(x + ((size_t)chunk * CHUNK_ROWS + w * 8) * DIM)
                        + lane * 16;
        #pragma unroll
        for (int i = 0; i < 4; i++)
            cp16(xw_u32 + lane * 16 + i * 512, src + i * 512);
        cp_commit();
    }

    int buf = 0;
    for (; chunk < nChunks; chunk += GRID) {
        const int row0 = chunk * CHUNK_ROWS + w * 8;
        const int next = chunk + GRID;
        if (next < nChunks) {
            const char* src = (const char*)(x + ((size_t)next * CHUNK_ROWS + w * 8) * DIM)
                            + lane * 16;
            const unsigned d32 = xw_u32 + (buf ^ 1) * 2048 + lane * 16;
            #pragma unroll
            for (int i = 0; i < 4; i++)
                cp16(d32 + i * 512, src + i * 512);
            cp_commit();
            cp_wait1();      // current chunk's group complete
        } else {
            cp_wait0();
        }
        __syncwarp();        // all lanes' copies visible warp-wide
        const float* xs = xw + buf * 512;

        // ---- dot products: 8 rows x 8 k-pair groups, packed f32x2 FMAs
        ull acc[8][8];
        #pragma unroll
        for (int r = 0; r < 8; r++)
            #pragma unroll
            for (int g = 0; g < 8; g++) acc[r][g] = 0ull;

        #pragma unroll 2
        for (int d2 = 0; d2 < DIM / 2; d2++) {
            float2 av2[8];                           // broadcast LDS.64 per row
            #pragma unroll
            for (int r = 0; r < 8; r++)
                av2[r] = *(const float2*)(xs + r * DIM + d2 * 2);
            #pragma unroll
            for (int dd = 0; dd < 2; dd++) {
                const float* er = Esm + (d2 * 2 + dd) * KCB + 2 * lane;
                ull bv[8];
                #pragma unroll
                for (int g = 0; g < 8; g++)
                    bv[g] = *reinterpret_cast<const ull*>(er + 64 * g);
                #pragma unroll
                for (int r = 0; r < 8; r++) {
                    ull av = pack2(dd == 0 ? av2[r].x : av2[r].y);
                    #pragma unroll
                    for (int g = 0; g < 8; g++)
                        asm("fma.rn.f32x2 %0, %1, %2, %0;"
                            : "+l"(acc[r][g]) : "l"(av), "l"(bv[g]));
                }
            }
        }

        // ---- epilogue per row (overlaps other warps' FMA bursts)
        #pragma unroll
        for (int r = 0; r < 8; r++) {
            const int row = row0 + r;
            const float a0 = xs[r * DIM + lane];
            const float a1 = xs[r * DIM + 32 + lane];
            float s = a0 * a0 + a1 * a1;
            #pragma unroll
            for (int o = 16; o > 0; o >>= 1) s += __shfl_xor_sync(~0u, s, o);
            const float xsq = s;

            float bestv = __int_as_float(0x7F800000);  // +inf
            int   besti = 0;
            float* dp = dist + (size_t)row * KCB + 2 * lane;
            #pragma unroll
            for (int g = 0; g < 8; g++) {
                const int k0 = 2 * lane + 64 * g;
                float t0, t1;
                unpack2(acc[r][g], t0, t1);
                float d0 = fmaf(-2.f, t0, xsq + e0r[g]);
                float d1 = fmaf(-2.f, t1, xsq + e1r[g]);
                __stcs((float2*)(dp + 64 * g), make_float2(d0, d1));
                if (d0 < bestv) { bestv = d0; besti = k0; }
                if (d1 < bestv) { bestv = d1; besti = k0 + 1; }
            }
            #pragma unroll
            for (int o = 16; o > 0; o >>= 1) {
                float ov = __shfl_xor_sync(~0u, bestv, o);
                int   oi = __shfl_xor_sync(~0u, besti, o);
                if (ov < bestv || (ov == bestv && oi < besti)) { bestv = ov; besti = oi; }
            }
            const int bk = besti;

            const float q0 = __ldg(g_ET + bk * DIM + lane);
            const float q1 = __ldg(g_ET + bk * DIM + 32 + lane);
            __stcs(quant + (size_t)row * DIM + lane,      a0 + (q0 - a0));
            __stcs(quant + (size_t)row * DIM + 32 + lane, a1 + (q1 - a1));
            const float e0 = q0 - a0, e1 = q1 - a1;
            lossAcc += e0 * e0 + e1 * e1;

            float* ep = enc + (size_t)row * KCB + 2 * lane;
            #pragma unroll
            for (int g = 0; g < 8; g++) {
                const int k0 = 2 * lane + 64 * g;
                __stcs((float2*)(ep + 64 * g),
                       make_float2(k0 == bk ? 1.f : 0.f, (k0 + 1) == bk ? 1.f : 0.f));
            }
            if (lane == 0) {
                idxf[row] = (float)bk;
                atomicAdd(&hist[bk], 1);
            }
        }
        buf ^= 1;
    }

    // block reductions
    #pragma unroll
    for (int o = 16; o > 0; o >>= 1) lossAcc += __shfl_xor_sync(~0u, lossAcc, o);
    __syncthreads();
    if (lane == 0) lred[w] = lossAcc;
    __syncthreads();
    if (tid == 0) {
        float s = 0.f;
        #pragma unroll
        for (int i = 0; i < 8; i++) s += lred[i];
        atomicAdd(&g_loss, s);
    }
    for (int i = tid; i < KCB; i += NTH)
        if (hist[i]) atomicAdd(&g_cnt[i], hist[i]);
}

// ---------------- finalize: loss + perplexity ----------------
__global__ void vq_finalize(float* __restrict__ loss_out,
                            float* __restrict__ perp_out,
                            float invN, float invND)
{
    __shared__ float red[16];
    int t = threadIdx.x;  // 512
    float p = (float)g_cnt[t] * invN;
    float v = p * logf(p + 1e-10f);
    #pragma unroll
    for (int o = 16; o > 0; o >>= 1) v += __shfl_xor_sync(~0u, v, o);
    if ((t & 31) == 0) red[t >> 5] = v;
    __syncthreads();
    if (t == 0) {
        float s = 0.f;
        #pragma unroll
        for (int i = 0; i < 16; i++) s += red[i];
        *perp_out = expf(-s);
        *loss_out = 1.25f * g_loss * invND;   // q_latent + 0.25*e_latent
    }
}

// ---------------- launch ----------------
extern "C" void kernel_launch(void* const* d_in, const int* in_sizes, int n_in,
                              void* d_out, int out_size)
{
    const float* x = (const float*)d_in[0];
    // d_in[1] = context (unused)
    const float* E = (const float*)d_in[2];
    const int N = in_sizes[0] / DIM;      // 65536

    float* out = (float*)d_out;
    const size_t q_off    = 0;
    const size_t loss_off = (size_t)N * DIM;
    const size_t perp_off = loss_off + 1;
    const size_t enc_off  = perp_off + 1;
    const size_t idx_off  = enc_off + (size_t)N * KCB;
    const size_t dist_off = idx_off + (size_t)N;

    cudaFuncSetAttribute(vq_main, cudaFuncAttributeMaxDynamicSharedMemorySize,
                         SMEM_BYTES);

    dim3 pgrid(KCB / 32, DIM / 32);
    vq_prep<<<pgrid, dim3(32, 32)>>>(E);
    vq_main<<<GRID, NTH, SMEM_BYTES>>>(x, E,
                                       out + q_off, out + enc_off,
                                       out + idx_off, out + dist_off, N);
    vq_finalize<<<1, KCB>>>(out + loss_off, out + perp_off,
                            1.0f / (float)N, 1.0f / ((float)N * (float)DIM));
}

// round 8
// speedup vs baseline: 1.4844x; 1.0069x over previous
#include <cuda_runtime.h>
#include <math.h>

#define DIM        64
#define KCB        512
#define CHUNK_ROWS 64
#define NTH        512
#define WARPS      16
#define ROWS_PW    4
#define GRID       148

typedef unsigned long long ull;

// ---------------- device scratch (no allocation allowed) ----------------
__device__ float g_ET[KCB * DIM];   // transposed codebook [K][D]
__device__ float g_loss;            // sum of (q-x)^2
__device__ int   g_cnt[KCB];        // histogram of indices

// ---------------- helpers ----------------
__device__ __forceinline__ ull pack2(float x) {
    ull r;
    asm("mov.b64 %0, {%1, %1};" : "=l"(r) : "f"(x));
    return r;
}
__device__ __forceinline__ void unpack2(ull v, float& lo, float& hi) {
    asm("mov.b64 {%0, %1}, %2;" : "=f"(lo), "=f"(hi) : "l"(v));
}
__device__ __forceinline__ void cp16(unsigned dst, const void* src) {
    asm volatile("cp.async.cg.shared.global [%0], [%1], 16;" :: "r"(dst), "l"(src));
}
__device__ __forceinline__ void cp_commit() {
    asm volatile("cp.async.commit_group;");
}
__device__ __forceinline__ void cp_wait0() {
    asm volatile("cp.async.wait_group 0;");
}
__device__ __forceinline__ void cp_wait1() {
    asm volatile("cp.async.wait_group 1;");
}

// ---------------- prep: tiled transpose (coalesced both sides) ----------
__global__ void vq_prep(const float* __restrict__ E) {
    __shared__ float t[32][33];
    const int kb = blockIdx.x * 32, db = blockIdx.y * 32;
    t[threadIdx.y][threadIdx.x] = E[(db + threadIdx.y) * KCB + kb + threadIdx.x];
    __syncthreads();
    g_ET[(kb + threadIdx.y) * DIM + db + threadIdx.x] = t[threadIdx.x][threadIdx.y];
    if (blockIdx.x == 0 && blockIdx.y == 0) {
        int id = threadIdx.y * 32 + threadIdx.x;
        if (id < KCB) g_cnt[id] = 0;
        if (id == 0)  g_loss = 0.f;
    }
}

// ---------------- main kernel ----------------
// smem: Esm[64*512] | per-warp xs (16 warps x 2 bufs x 256 floats) | esq | hist | lred
static const int XS_OFF     = DIM * KCB;                        // 32768
static const int XS_FLOATS  = WARPS * 2 * (ROWS_PW * DIM);      // 8192
static const int ESQ_OFF    = XS_OFF + XS_FLOATS;               // 40960
static const int HIST_OFF   = ESQ_OFF + KCB;                    // 41472
static const int LRED_OFF   = HIST_OFF + KCB;                   // 41984
static const int SMEM_BYTES = (LRED_OFF + WARPS) * 4;           // ~168 KB

__global__ void __launch_bounds__(NTH, 1)
vq_main(const float* __restrict__ x, const float* __restrict__ E,
        float* __restrict__ quant, float* __restrict__ enc,
        float* __restrict__ idxf, float* __restrict__ dist, int nRows)
{
    extern __shared__ float sm[];
    float* Esm  = sm;
    float* esq  = sm + ESQ_OFF;
    int*   hist = (int*)(sm + HIST_OFF);
    float* lred = sm + LRED_OFF;

    const int tid  = threadIdx.x;
    const int lane = tid & 31;
    const int w    = tid >> 5;

    unsigned smem_u32;
    {
        void* p = sm;
        asm("{ .reg .u64 t; cvta.to.shared.u64 t, %1; cvt.u32.u64 %0, t; }"
            : "=r"(smem_u32) : "l"(p));
    }
    // per-warp private x tile: 2 buffers x 256 floats (4 rows x 64)
    float* xw = sm + XS_OFF + w * 512;
    const unsigned xw_u32 = smem_u32 + (XS_OFF + w * 512) * 4;

    // codebook -> smem (float4, coalesced)
    for (int i = tid; i < (DIM * KCB) / 4; i += NTH)
        ((float4*)Esm)[i] = ((const float4*)E)[i];
    __syncthreads();
    // esq (column reads, conflict-free)
    for (int k = tid; k < KCB; k += NTH) {
        float s = 0.f;
        #pragma unroll
        for (int d = 0; d < DIM; d++) {
            float v = Esm[d * KCB + k];
            s = fmaf(v, v, s);
        }
        esq[k]  = s;
        hist[k] = 0;
    }
    __syncthreads();   // last block-wide barrier until the final reduction

    float lossAcc = 0.f;
    const int nChunks = nRows / CHUNK_ROWS;

    // warp-autonomous main loop: no block barriers, warps drift freely
    int chunk = blockIdx.x;
    if (chunk < nChunks) {
        const char* src =
            (const char*)(x + ((size_t)chunk * CHUNK_ROWS + w * ROWS_PW) * DIM)
            + lane * 16;
        #pragma unroll
        for (int i = 0; i < 2; i++)
            cp16(xw_u32 + lane * 16 + i * 512, src + i * 512);
        cp_commit();
    }

    int buf = 0;
    for (; chunk < nChunks; chunk += GRID) {
        const int row0 = chunk * CHUNK_ROWS + w * ROWS_PW;
        const int next = chunk + GRID;
        if (next < nChunks) {
            const char* src =
                (const char*)(x + ((size_t)next * CHUNK_ROWS + w * ROWS_PW) * DIM)
                + lane * 16;
            const unsigned d32 = xw_u32 + (buf ^ 1) * 1024 + lane * 16;
            #pragma unroll
            for (int i = 0; i < 2; i++)
                cp16(d32 + i * 512, src + i * 512);
            cp_commit();
            cp_wait1();      // current chunk's group complete
        } else {
            cp_wait0();
        }
        __syncwarp();
        const float* xs = xw + buf * 256;

        // ---- dot products: 4 rows x 8 k-pair groups, packed f32x2 FMAs
        ull acc[ROWS_PW][8];
        #pragma unroll
        for (int r = 0; r < ROWS_PW; r++)
            #pragma unroll
            for (int g = 0; g < 8; g++) acc[r][g] = 0ull;

        #pragma unroll 2
        for (int d2 = 0; d2 < DIM / 2; d2++) {
            float2 av2[ROWS_PW];                     // broadcast LDS.64 per row
            #pragma unroll
            for (int r = 0; r < ROWS_PW; r++)
                av2[r] = *(const float2*)(xs + r * DIM + d2 * 2);
            #pragma unroll
            for (int dd = 0; dd < 2; dd++) {
                const float* er = Esm + (d2 * 2 + dd) * KCB + 2 * lane;
                ull av[ROWS_PW];
                #pragma unroll
                for (int r = 0; r < ROWS_PW; r++)
                    av[r] = pack2(dd == 0 ? av2[r].x : av2[r].y);
                #pragma unroll
                for (int h = 0; h < 2; h++) {        // halve bv register window
                    ull bv[4];
                    #pragma unroll
                    for (int g4 = 0; g4 < 4; g4++)
                        bv[g4] = *reinterpret_cast<const ull*>(er + 64 * (h * 4 + g4));
                    #pragma unroll
                    for (int r = 0; r < ROWS_PW; r++)
                        #pragma unroll
                        for (int g4 = 0; g4 < 4; g4++)
                            asm("fma.rn.f32x2 %0, %1, %2, %0;"
                                : "+l"(acc[r][h * 4 + g4]) : "l"(av[r]), "l"(bv[g4]));
                }
            }
        }

        // ---- epilogue per row (overlaps other warps' FMA bursts)
        #pragma unroll
        for (int r = 0; r < ROWS_PW; r++) {
            const int row = row0 + r;
            const float a0 = xs[r * DIM + lane];
            const float a1 = xs[r * DIM + 32 + lane];
            float s = a0 * a0 + a1 * a1;
            #pragma unroll
            for (int o = 16; o > 0; o >>= 1) s += __shfl_xor_sync(~0u, s, o);
            const float xsq = s;

            float bestv = __int_as_float(0x7F800000);  // +inf
            int   besti = 0;
            float* dp = dist + (size_t)row * KCB + 2 * lane;
            #pragma unroll
            for (int g = 0; g < 8; g++) {
                const int k0 = 2 * lane + 64 * g;
                float2 es = *(const float2*)(esq + k0);
                float t0, t1;
                unpack2(acc[r][g], t0, t1);
                float d0 = fmaf(-2.f, t0, xsq + es.x);
                float d1 = fmaf(-2.f, t1, xsq + es.y);
                __stcs((float2*)(dp + 64 * g), make_float2(d0, d1));
                if (d0 < bestv) { bestv = d0; besti = k0; }
                if (d1 < bestv) { bestv = d1; besti = k0 + 1; }
            }
            #pragma unroll
            for (int o = 16; o > 0; o >>= 1) {
                float ov = __shfl_xor_sync(~0u, bestv, o);
                int   oi = __shfl_xor_sync(~0u, besti, o);
                if (ov < bestv || (ov == bestv && oi < besti)) { bestv = ov; besti = oi; }
            }
            const int bk = besti;

            const float q0 = __ldg(g_ET + bk * DIM + lane);
            const float q1 = __ldg(g_ET + bk * DIM + 32 + lane);
            __stcs(quant + (size_t)row * DIM + lane,      a0 + (q0 - a0));
            __stcs(quant + (size_t)row * DIM + 32 + lane, a1 + (q1 - a1));
            const float e0 = q0 - a0, e1 = q1 - a1;
            lossAcc += e0 * e0 + e1 * e1;

            float* ep = enc + (size_t)row * KCB + 2 * lane;
            #pragma unroll
            for (int g = 0; g < 8; g++) {
                const int k0 = 2 * lane + 64 * g;
                __stcs((float2*)(ep + 64 * g),
                       make_float2(k0 == bk ? 1.f : 0.f, (k0 + 1) == bk ? 1.f : 0.f));
            }
            if (lane == 0) {
                idxf[row] = (float)bk;
                atomicAdd(&hist[bk], 1);
            }
        }
        buf ^= 1;
    }

    // block reductions
    #pragma unroll
    for (int o = 16; o > 0; o >>= 1) lossAcc += __shfl_xor_sync(~0u, lossAcc, o);
    __syncthreads();
    if (lane == 0) lred[w] = lossAcc;
    __syncthreads();
    if (tid == 0) {
        float s = 0.f;
        #pragma unroll
        for (int i = 0; i < WARPS; i++) s += lred[i];
        atomicAdd(&g_loss, s);
    }
    for (int i = tid; i < KCB; i += NTH)
        if (hist[i]) atomicAdd(&g_cnt[i], hist[i]);
}

// ---------------- finalize: loss + perplexity ----------------
__global__ void vq_finalize(float* __restrict__ loss_out,
                            float* __restrict__ perp_out,
                            float invN, float invND)
{
    __shared__ float red[16];
    int t = threadIdx.x;  // 512
    float p = (float)g_cnt[t] * invN;
    float v = p * logf(p + 1e-10f);
    #pragma unroll
    for (int o = 16; o > 0; o >>= 1) v += __shfl_xor_sync(~0u, v, o);
    if ((t & 31) == 0) red[t >> 5] = v;
    __syncthreads();
    if (t == 0) {
        float s = 0.f;
        #pragma unroll
        for (int i = 0; i < 16; i++) s += red[i];
        *perp_out = expf(-s);
        *loss_out = 1.25f * g_loss * invND;   // q_latent + 0.25*e_latent
    }
}

// ---------------- launch ----------------
extern "C" void kernel_launch(void* const* d_in, const int* in_sizes, int n_in,
                              void* d_out, int out_size)
{
    const float* x = (const float*)d_in[0];
    // d_in[1] = context (unused)
    const float* E = (const float*)d_in[2];
    const int N = in_sizes[0] / DIM;      // 65536

    float* out = (float*)d_out;
    const size_t q_off    = 0;
    const size_t loss_off = (size_t)N * DIM;
    const size_t perp_off = loss_off + 1;
    const size_t enc_off  = perp_off + 1;
    const size_t idx_off  = enc_off + (size_t)N * KCB;
    const size_t dist_off = idx_off + (size_t)N;

    cudaFuncSetAttribute(vq_main, cudaFuncAttributeMaxDynamicSharedMemorySize,
                         SMEM_BYTES);

    dim3 pgrid(KCB / 32, DIM / 32);
    vq_prep<<<pgrid, dim3(32, 32)>>>(E);
    vq_main<<<GRID, NTH, SMEM_BYTES>>>(x, E,
                                       out + q_off, out + enc_off,
                                       out + idx_off, out + dist_off, N);
    vq_finalize<<<1, KCB>>>(out + loss_off, out + perp_off,
                            1.0f / (float)N, 1.0f / ((float)N * (float)DIM));
}